// round 5
// baseline (speedup 1.0000x reference)
#include <cuda_runtime.h>

#define NCTA   128
#define TPB    256
#define PP     1024
#define DD     32
#define RS     1032
#define MAXIT  30
#define EPSV   0.1f
#define LN2F   0.69314718055994530942f
#define ALPHA  14.4269504088896340736f   /* 1/(eps*ln2) */
#define THRESH 0.1f

typedef unsigned long long u64;

__device__ float    g_Lp[4 * PP * 32];     // transposed column partials [nb][col][sub]
__device__ float    g_err[MAXIT * 4];      // per-iter, per-batch err sums
__device__ double   g_cost[4];
__device__ unsigned g_cnt_b[4];
__device__ unsigned g_cnt_root = 0;
__device__ volatile unsigned g_gen = 0;

struct Smem {
    float  K2[32 * RS];        // 132096 B
    float  bb[PP];             // B vector (log2 domain)
    float  lnu2[PP];           // log2(nu + 1e-8), full batch column set
    float  ystage[256 * DD];   // setup staging
    double redd[TPB];
    float  A2s[32];
    float  lmu2s[32];
    float  errAcc;
    float  Sx, Sy;
};

__device__ __forceinline__ float ex2f(float x){ float r; asm("ex2.approx.ftz.f32 %0, %1;" : "=f"(r) : "f"(x)); return r; }
__device__ __forceinline__ float lg2f(float x){ float r; asm("lg2.approx.f32 %0, %1;" : "=f"(r) : "f"(x)); return r; }
__device__ __forceinline__ u64 pk2(float lo, float hi){ u64 r; asm("mov.b64 %0, {%1, %2};" : "=l"(r) : "f"(lo), "f"(hi)); return r; }
__device__ __forceinline__ void upk2(u64 v, float& lo, float& hi){ asm("mov.b64 {%0, %1}, %2;" : "=f"(lo), "=f"(hi) : "l"(v)); }
__device__ __forceinline__ void fma2(u64& d, u64 a, u64 b){ asm("fma.rn.f32x2 %0, %1, %2, %0;" : "+l"(d) : "l"(a), "l"(b)); }
__device__ __forceinline__ u64 add2(u64 a, u64 b){ u64 r; asm("add.rn.f32x2 %0, %1, %2;" : "=l"(r) : "l"(a), "l"(b)); return r; }

// 2-level tree barrier: 4 leaf counters (32 arrivals) -> root (4) -> g_gen
__device__ __forceinline__ void gbar(unsigned target, int nb) {
    __syncthreads();
    if (threadIdx.x == 0) {
        __threadfence();
        if (atomicAdd(&g_cnt_b[nb], 1u) == 31u) {
            if (atomicAdd(&g_cnt_root, 1u) == 3u) {
                g_cnt_root = 0;
                g_cnt_b[0] = 0; g_cnt_b[1] = 0; g_cnt_b[2] = 0; g_cnt_b[3] = 0;
                __threadfence();
                g_gen = target;
            }
        }
        while (g_gen != target) { }
        __threadfence();
    }
    __syncthreads();
}

__global__ void __launch_bounds__(TPB, 1)
sinkhorn_kernel(const float* __restrict__ gx, const float* __restrict__ gy,
                const float* __restrict__ gxw, const float* __restrict__ gyw,
                float* __restrict__ gout)
{
    extern __shared__ __align__(16) char smraw[];
    Smem* S = reinterpret_cast<Smem*>(smraw);

    const int tid  = threadIdx.x;
    const int lane = tid & 31;
    const int warp = tid >> 5;       // 0..7
    const int bid  = blockIdx.x;
    const int nb   = bid >> 5;
    const int sub  = bid & 31;
    const int r0   = sub * 32;

    const unsigned g0 = g_gen;
    unsigned bk = 0;

    // zero per-launch global state (disjoint slices, before first barrier)
    if (bid == 0) {
        for (int k = tid; k < MAXIT * 4; k += TPB) g_err[k] = 0.f;
        if (tid < 4) g_cost[tid] = 0.0;
    }

    // global weight sums (redundant per CTA, deterministic)
    {
        float px = 0.f, py = 0.f;
        for (int k = tid; k < 4096; k += TPB) { px += gxw[k]; py += gyw[k]; }
        S->redd[tid] = (double)px; __syncthreads();
        for (int s = TPB/2; s > 0; s >>= 1) { if (tid < s) S->redd[tid] += S->redd[tid+s]; __syncthreads(); }
        if (tid == 0) S->Sx = (float)S->redd[0];
        __syncthreads();
        S->redd[tid] = (double)py; __syncthreads();
        for (int s = TPB/2; s > 0; s >>= 1) { if (tid < s) S->redd[tid] += S->redd[tid+s]; __syncthreads(); }
        if (tid == 0) S->Sy = (float)S->redd[0];
        __syncthreads();
    }

    if (tid < 32) {
        S->lmu2s[tid] = lg2f(gxw[nb * PP + r0 + tid] / S->Sx + 1e-8f);
        S->A2s[tid]   = 0.f;
    }
    // full-batch log2(nu + 1e-8)
    for (int c = tid; c < PP; c += TPB)
        S->lnu2[c] = lg2f(gyw[nb * PP + c] / S->Sy + 1e-8f);

    // ---- build K2 = -C/(eps*ln2) in SMEM ----
    const float* ybase = gy + (size_t)nb * PP * DD;
    for (int c = tid; c < PP; c += TPB) {
        const float4* yc = (const float4*)(ybase + c * DD);
        float s = 0.f;
#pragma unroll
        for (int q = 0; q < 8; q++) { float4 v = yc[q]; s += v.x*v.x + v.y*v.y + v.z*v.z + v.w*v.w; }
        S->bb[c] = s * ALPHA;   // temp: ALPHA*|y|^2
    }
    float xv[32];
    {
        const float4* xr = (const float4*)(gx + (size_t)(nb * PP + r0 + lane) * DD);
#pragma unroll
        for (int q = 0; q < 8; q++) {
            float4 v = xr[q];
            xv[4*q] = v.x; xv[4*q+1] = v.y; xv[4*q+2] = v.z; xv[4*q+3] = v.w;
        }
    }
    float x2 = 0.f;
#pragma unroll
    for (int d = 0; d < 32; d++) x2 += xv[d] * xv[d];
    const float cx = ALPHA * x2;
    u64 xp[16];
#pragma unroll
    for (int q = 0; q < 16; q++) xp[q] = pk2(xv[2*q], xv[2*q+1]);
    __syncthreads();

    for (int chunk = 0; chunk < 4; chunk++) {
        const int j0 = chunk * 256;
        const float4* ysrc = (const float4*)(ybase + j0 * DD);
        float4* yst = (float4*)S->ystage;
#pragma unroll
        for (int q = 0; q < 8; q++) yst[tid + 256 * q] = ysrc[tid + 256 * q];
        __syncthreads();
#pragma unroll 4
        for (int m = 0; m < 32; m++) {
            const int jj = warp + 8 * m;
            const ulonglong2* yp = (const ulonglong2*)(S->ystage + jj * DD);
            u64 acc[4] = {0ull, 0ull, 0ull, 0ull};
#pragma unroll
            for (int q = 0; q < 8; q++) {
                ulonglong2 w = yp[q];
                fma2(acc[(2*q)   & 3], xp[2*q],     w.x);
                fma2(acc[(2*q+1) & 3], xp[2*q + 1], w.y);
            }
            u64 st = add2(add2(acc[0], acc[1]), add2(acc[2], acc[3]));
            float lo, hi; upk2(st, lo, hi);
            float dot = lo + hi;
            S->K2[lane * RS + j0 + jj] = fmaf(dot, 2.f * ALPHA, -(cx + S->bb[j0 + jj]));
        }
        __syncthreads();
    }

    gbar(g0 + (++bk), nb);   // setup done; g_err/g_cost zeroed & visible

    // ---- Sinkhorn iterations: ONE grid barrier each ----
    for (int iter = 0; iter <= MAXIT; iter++) {
        // (a) build B into bb: zero at iter 0, else combine partials from iter-1
        if (iter == 0) {
#pragma unroll
            for (int cc = 0; cc < 4; cc++) S->bb[tid + 256 * cc] = 0.f;
        } else {
#pragma unroll
            for (int cc = 0; cc < 4; cc++) {
                const int col = tid + 256 * cc;
                const float4* lp = (const float4*)(g_Lp + (((nb * PP + col) << 5)));
                float4 a0 = __ldcg(lp + 0), a1 = __ldcg(lp + 1), a2 = __ldcg(lp + 2), a3 = __ldcg(lp + 3);
                float4 a4 = __ldcg(lp + 4), a5 = __ldcg(lp + 5), a6 = __ldcg(lp + 6), a7 = __ldcg(lp + 7);
                float m01 = fmaxf(fmaxf(fmaxf(a0.x,a0.y),fmaxf(a0.z,a0.w)), fmaxf(fmaxf(a1.x,a1.y),fmaxf(a1.z,a1.w)));
                float m23 = fmaxf(fmaxf(fmaxf(a2.x,a2.y),fmaxf(a2.z,a2.w)), fmaxf(fmaxf(a3.x,a3.y),fmaxf(a3.z,a3.w)));
                float m45 = fmaxf(fmaxf(fmaxf(a4.x,a4.y),fmaxf(a4.z,a4.w)), fmaxf(fmaxf(a5.x,a5.y),fmaxf(a5.z,a5.w)));
                float m67 = fmaxf(fmaxf(fmaxf(a6.x,a6.y),fmaxf(a6.z,a6.w)), fmaxf(fmaxf(a7.x,a7.y),fmaxf(a7.z,a7.w)));
                float m = fmaxf(fmaxf(m01, m23), fmaxf(m45, m67));
                float s =
                    ex2f(a0.x-m)+ex2f(a0.y-m)+ex2f(a0.z-m)+ex2f(a0.w-m) +
                    ex2f(a1.x-m)+ex2f(a1.y-m)+ex2f(a1.z-m)+ex2f(a1.w-m) +
                    ex2f(a2.x-m)+ex2f(a2.y-m)+ex2f(a2.z-m)+ex2f(a2.w-m) +
                    ex2f(a3.x-m)+ex2f(a3.y-m)+ex2f(a3.z-m)+ex2f(a3.w-m) +
                    ex2f(a4.x-m)+ex2f(a4.y-m)+ex2f(a4.z-m)+ex2f(a4.w-m) +
                    ex2f(a5.x-m)+ex2f(a5.y-m)+ex2f(a5.z-m)+ex2f(a5.w-m) +
                    ex2f(a6.x-m)+ex2f(a6.y-m)+ex2f(a6.z-m)+ex2f(a6.w-m) +
                    ex2f(a7.x-m)+ex2f(a7.y-m)+ex2f(a7.z-m)+ex2f(a7.w-m);
                S->bb[col] = S->lnu2[col] - (m + lg2f(s));
            }
        }
        if (tid == 0) S->errAcc = 0.f;
        __syncthreads();

        // (b) termination: MAXIT, or global err from iter-1 below threshold
        if (iter == MAXIT) break;
        if (iter > 0) {
            const float* e = &g_err[(iter - 1) * 4];
            float ev = __ldcg(e + 0) + __ldcg(e + 1) + __ldcg(e + 2) + __ldcg(e + 3);
            if (ev * (EPSV * LN2F * 0.25f) < THRESH) break;
        }

        // (c) row (u) update: warp handles 4 rows
#pragma unroll
        for (int k = 0; k < 4; k++) {
            const int r = warp * 4 + k;
            const float4* kr = (const float4*)(S->K2 + r * RS);
            const float4* b4 = (const float4*)S->bb;
            float4 t[8];
            float m = -1e30f;
#pragma unroll
            for (int q = 0; q < 8; q++) {
                float4 a = kr[lane + 32 * q], b = b4[lane + 32 * q];
                t[q].x = a.x + b.x; t[q].y = a.y + b.y;
                t[q].z = a.z + b.z; t[q].w = a.w + b.w;
                m = fmaxf(m, fmaxf(fmaxf(t[q].x, t[q].y), fmaxf(t[q].z, t[q].w)));
            }
#pragma unroll
            for (int o = 16; o; o >>= 1) m = fmaxf(m, __shfl_xor_sync(0xffffffffu, m, o));
            float s = 0.f;
#pragma unroll
            for (int q = 0; q < 8; q++)
                s += ex2f(t[q].x - m) + ex2f(t[q].y - m) + ex2f(t[q].z - m) + ex2f(t[q].w - m);
#pragma unroll
            for (int o = 16; o; o >>= 1) s += __shfl_xor_sync(0xffffffffu, s, o);
            if (lane == 0) {
                float an = S->lmu2s[r] - (m + lg2f(s));
                atomicAdd(&S->errAcc, fabsf(an - S->A2s[r]));
                S->A2s[r] = an;
            }
        }
        __syncthreads();
        if (tid == 0) atomicAdd(&g_err[iter * 4 + nb], S->errAcc);

        // (d) column partial LSE over own 32 rows -> transposed g_Lp
        {
            float ar[32];
#pragma unroll
            for (int r = 0; r < 32; r++) ar[r] = S->A2s[r];
            float m0=-1e30f, m1=-1e30f, m2=-1e30f, m3=-1e30f;
#pragma unroll
            for (int r = 0; r < 32; r++) {
                const float* kr = S->K2 + r * RS + tid;
                float a = ar[r];
                m0 = fmaxf(m0, kr[0]   + a);
                m1 = fmaxf(m1, kr[256] + a);
                m2 = fmaxf(m2, kr[512] + a);
                m3 = fmaxf(m3, kr[768] + a);
            }
            float s0=0.f, s1=0.f, s2=0.f, s3=0.f;
#pragma unroll
            for (int r = 0; r < 32; r++) {
                const float* kr = S->K2 + r * RS + tid;
                float a = ar[r];
                s0 += ex2f(kr[0]   + a - m0);
                s1 += ex2f(kr[256] + a - m1);
                s2 += ex2f(kr[512] + a - m2);
                s3 += ex2f(kr[768] + a - m3);
            }
            const int base = (nb * PP) << 5;
            __stcg(&g_Lp[base + ((tid      ) << 5) + sub], m0 + lg2f(s0));
            __stcg(&g_Lp[base + ((tid + 256) << 5) + sub], m1 + lg2f(s1));
            __stcg(&g_Lp[base + ((tid + 512) << 5) + sub], m2 + lg2f(s2));
            __stcg(&g_Lp[base + ((tid + 768) << 5) + sub], m3 + lg2f(s3));
        }
        gbar(g0 + (++bk), nb);
    }

    // ---- final cost: cost_n = -eps*ln2 * sum 2^(K2+A+B) * K2  (bb holds final B) ----
    {
        float ar[32];
#pragma unroll
        for (int r = 0; r < 32; r++) ar[r] = S->A2s[r];
        const float bc0 = S->bb[tid],       bc1 = S->bb[tid + 256];
        const float bc2 = S->bb[tid + 512], bc3 = S->bb[tid + 768];
        float acc = 0.f;
#pragma unroll 8
        for (int r = 0; r < 32; r++) {
            const float* kr = S->K2 + r * RS + tid;
            float a = ar[r];
            float k0 = kr[0], k1 = kr[256], k2 = kr[512], k3 = kr[768];
            acc = fmaf(ex2f(k0 + a + bc0), k0, acc);
            acc = fmaf(ex2f(k1 + a + bc1), k1, acc);
            acc = fmaf(ex2f(k2 + a + bc2), k2, acc);
            acc = fmaf(ex2f(k3 + a + bc3), k3, acc);
        }
        S->redd[tid] = (double)acc; __syncthreads();
        for (int s = TPB/2; s > 0; s >>= 1) { if (tid < s) S->redd[tid] += S->redd[tid+s]; __syncthreads(); }
        if (tid == 0) atomicAdd(&g_cost[nb], S->redd[0]);
    }
    gbar(g0 + (++bk), nb);
    if (sub == 0 && tid == 0) {
        double cv = __ldcg(&g_cost[nb]);
        gout[nb] = (float)(-(double)EPSV * (double)LN2F * cv);
    }
}

extern "C" void kernel_launch(void* const* d_in, const int* in_sizes, int n_in,
                              void* d_out, int out_size) {
    const float* x  = (const float*)d_in[0];
    const float* y  = (const float*)d_in[1];
    const float* xw = (const float*)d_in[2];
    const float* yw = (const float*)d_in[3];
    float* out = (float*)d_out;
    size_t smem = sizeof(Smem);
    cudaFuncSetAttribute(sinkhorn_kernel, cudaFuncAttributeMaxDynamicSharedMemorySize, (int)smem);
    sinkhorn_kernel<<<NCTA, TPB, smem>>>(x, y, xw, yw, out);
}

// round 6
// speedup vs baseline: 1.2174x; 1.2174x over previous
#include <cuda_runtime.h>

#define NCTA   128
#define TPB    256
#define PP     1024
#define DD     32
#define RS     1032
#define MAXIT  30
#define EPSV   0.1f
#define LN2F   0.69314718055994530942f
#define ALPHA  14.4269504088896340736f   /* 1/(eps*ln2) */
#define THRESH 0.1f

typedef unsigned long long u64;

__device__ float    g_b2[4096];            // B per (batch, col)
__device__ float2   g_cp[NCTA * PP];       // per-CTA column partials (m, s)
__device__ float    g_err[MAXIT * 4];      // per-iter per-batch |dA| sums
__device__ double   g_cost[4];
__device__ volatile unsigned g_flags[NCTA * 8];   // 32B-spaced arrival flags

struct Smem {
    float  K2[32 * RS];        // 132096 B
    float  bb[PP];             // current B vector (log2 domain)
    float  lnu2[PP];           // log2(nu + 1e-8) full batch
    float  colShift[PP];       // per-column LSE shift (this CTA's 32 rows)
    float  ystage[256 * DD];   // setup staging (32 KB)
    double redd[TPB];
    float2 cmb[8][32];         // phase-2 combine tree
    float  A2s[32];
    float  lmu2s[32];
    float  rowShift[32];
    float  errAcc;
    float  Sx, Sy;
};

__device__ __forceinline__ float ex2f(float x){ float r; asm("ex2.approx.ftz.f32 %0, %1;" : "=f"(r) : "f"(x)); return r; }
__device__ __forceinline__ float lg2f(float x){ float r; asm("lg2.approx.f32 %0, %1;" : "=f"(r) : "f"(x)); return r; }
__device__ __forceinline__ u64 pk2(float lo, float hi){ u64 r; asm("mov.b64 %0, {%1, %2};" : "=l"(r) : "f"(lo), "f"(hi)); return r; }
__device__ __forceinline__ void upk2(u64 v, float& lo, float& hi){ asm("mov.b64 {%0, %1}, %2;" : "=f"(lo), "=f"(hi) : "l"(v)); }
__device__ __forceinline__ void fma2(u64& d, u64 a, u64 b){ asm("fma.rn.f32x2 %0, %1, %2, %0;" : "+l"(d) : "l"(a), "l"(b)); }
__device__ __forceinline__ u64 add2(u64 a, u64 b){ u64 r; asm("add.rn.f32x2 %0, %1, %2;" : "=l"(r) : "l"(a), "l"(b)); return r; }

// Distributed flag barrier: CTA i writes flag i; 128 threads poll one flag each.
__device__ __forceinline__ void gbar(unsigned target, int bid) {
    __syncthreads();
    if (threadIdx.x == 0) {
        __threadfence();
        g_flags[bid * 8] = target;
    }
    if (threadIdx.x < NCTA) {
        if ((int)(g_flags[threadIdx.x * 8] - target) < 0) {
            while ((int)(g_flags[threadIdx.x * 8] - target) < 0) __nanosleep(64);
        }
        __threadfence();
    }
    __syncthreads();
}

__global__ void __launch_bounds__(TPB, 1)
sinkhorn_kernel(const float* __restrict__ gx, const float* __restrict__ gy,
                const float* __restrict__ gxw, const float* __restrict__ gyw,
                float* __restrict__ gout)
{
    extern __shared__ __align__(16) char smraw[];
    Smem* S = reinterpret_cast<Smem*>(smraw);

    const int tid  = threadIdx.x;
    const int lane = tid & 31;
    const int warp = tid >> 5;       // 0..7
    const int bid  = blockIdx.x;
    const int nb   = bid >> 5;
    const int sub  = bid & 31;
    const int r0   = sub * 32;

    const unsigned g0 = g_flags[bid * 8];   // own flag == global quiescent value
    unsigned bk = 0;

    // zero per-launch global accumulators (before first barrier)
    if (bid == 0) {
        for (int k = tid; k < MAXIT * 4; k += TPB) g_err[k] = 0.f;
        if (tid < 4) g_cost[tid] = 0.0;
    }

    // global weight sums (redundant per CTA, deterministic)
    {
        float px = 0.f, py = 0.f;
        for (int k = tid; k < 4096; k += TPB) { px += gxw[k]; py += gyw[k]; }
        S->redd[tid] = (double)px; __syncthreads();
        for (int s = TPB/2; s > 0; s >>= 1) { if (tid < s) S->redd[tid] += S->redd[tid+s]; __syncthreads(); }
        if (tid == 0) S->Sx = (float)S->redd[0];
        __syncthreads();
        S->redd[tid] = (double)py; __syncthreads();
        for (int s = TPB/2; s > 0; s >>= 1) { if (tid < s) S->redd[tid] += S->redd[tid+s]; __syncthreads(); }
        if (tid == 0) S->Sy = (float)S->redd[0];
        __syncthreads();
    }

    if (tid < 32) {
        S->lmu2s[tid] = lg2f(gxw[nb * PP + r0 + tid] / S->Sx + 1e-8f);
        S->A2s[tid]   = 0.f;
    }
    for (int c = tid; c < PP; c += TPB)
        S->lnu2[c] = lg2f(gyw[nb * PP + c] / S->Sy + 1e-8f);

    // ---- build K2 = -C/(eps*ln2) in SMEM ----
    const float* ybase = gy + (size_t)nb * PP * DD;
    for (int c = tid; c < PP; c += TPB) {
        const float4* yc = (const float4*)(ybase + c * DD);
        float s = 0.f;
#pragma unroll
        for (int q = 0; q < 8; q++) { float4 v = yc[q]; s += v.x*v.x + v.y*v.y + v.z*v.z + v.w*v.w; }
        S->bb[c] = s * ALPHA;   // temp: ALPHA*|y|^2
    }
    float xv[32];
    {
        const float4* xr = (const float4*)(gx + (size_t)(nb * PP + r0 + lane) * DD);
#pragma unroll
        for (int q = 0; q < 8; q++) {
            float4 v = xr[q];
            xv[4*q] = v.x; xv[4*q+1] = v.y; xv[4*q+2] = v.z; xv[4*q+3] = v.w;
        }
    }
    float x2 = 0.f;
#pragma unroll
    for (int d = 0; d < 32; d++) x2 += xv[d] * xv[d];
    const float cx = ALPHA * x2;
    u64 xp[16];
#pragma unroll
    for (int q = 0; q < 16; q++) xp[q] = pk2(xv[2*q], xv[2*q+1]);
    __syncthreads();

    for (int chunk = 0; chunk < 4; chunk++) {
        const int j0 = chunk * 256;
        const float4* ysrc = (const float4*)(ybase + j0 * DD);
        float4* yst = (float4*)S->ystage;
#pragma unroll
        for (int q = 0; q < 8; q++) yst[tid + 256 * q] = ysrc[tid + 256 * q];
        __syncthreads();
#pragma unroll 4
        for (int m = 0; m < 32; m++) {
            const int jj = warp + 8 * m;
            const ulonglong2* yp = (const ulonglong2*)(S->ystage + jj * DD);
            u64 acc[4] = {0ull, 0ull, 0ull, 0ull};
#pragma unroll
            for (int q = 0; q < 8; q++) {
                ulonglong2 w = yp[q];
                fma2(acc[(2*q)   & 3], xp[2*q],     w.x);
                fma2(acc[(2*q+1) & 3], xp[2*q + 1], w.y);
            }
            u64 st = add2(add2(acc[0], acc[1]), add2(acc[2], acc[3]));
            float lo, hi; upk2(st, lo, hi);
            float dot = lo + hi;
            S->K2[lane * RS + j0 + jj] = fmaf(dot, 2.f * ALPHA, -(cx + S->bb[j0 + jj]));
        }
        __syncthreads();
    }

    // ---- row maxes of K2 (iter-0 shift; B=0 at iter 0 so this is the true max) ----
#pragma unroll
    for (int k = 0; k < 4; k++) {
        const int r = warp * 4 + k;
        const float4* kr = (const float4*)(S->K2 + r * RS);
        float m = -1e30f;
#pragma unroll
        for (int q = 0; q < 8; q++) {
            float4 a = kr[lane + 32 * q];
            m = fmaxf(m, fmaxf(fmaxf(a.x, a.y), fmaxf(a.z, a.w)));
        }
#pragma unroll
        for (int o = 16; o; o >>= 1) m = fmaxf(m, __shfl_xor_sync(0xffffffffu, m, o));
        if (lane == 0) S->rowShift[r] = m;
    }

    // bb = 0 for iteration 0
#pragma unroll
    for (int cc = 0; cc < 4; cc++) S->bb[tid + 256 * cc] = 0.f;

    gbar(g0 + (++bk), bid);   // g_err/g_cost zeroing visible

    const int c0 = 2 * tid, c1 = 2 * tid + 1, c2 = 2 * tid + 512, c3 = 2 * tid + 513;

    // ================= Sinkhorn iterations =================
    int iter = 0;
    for (;;) {
        // ---------- row (u) update: shift = prev row LSE ----------
        if (tid == 0) S->errAcc = 0.f;
        __syncthreads();
#pragma unroll
        for (int k = 0; k < 4; k++) {
            const int r = warp * 4 + k;
            const float m = S->rowShift[r];
            const float4* kr = (const float4*)(S->K2 + r * RS);
            const float4* b4 = (const float4*)S->bb;
            float s0 = 0.f, s1 = 0.f, s2 = 0.f, s3 = 0.f;
#pragma unroll
            for (int q = 0; q < 8; q++) {
                float4 a = kr[lane + 32 * q], b = b4[lane + 32 * q];
                s0 += ex2f(a.x + b.x - m);
                s1 += ex2f(a.y + b.y - m);
                s2 += ex2f(a.z + b.z - m);
                s3 += ex2f(a.w + b.w - m);
            }
            float s = (s0 + s1) + (s2 + s3);
#pragma unroll
            for (int o = 16; o; o >>= 1) s += __shfl_xor_sync(0xffffffffu, s, o);
            if (lane == 0) {
                float lse = m + lg2f(s);
                float an  = S->lmu2s[r] - lse;
                atomicAdd(&S->errAcc, fabsf(an - S->A2s[r]));
                S->A2s[r]      = an;
                S->rowShift[r] = lse;    // next iteration's shift
            }
        }
        __syncthreads();
        if (tid == 0) atomicAdd(&g_err[iter * 4 + nb], S->errAcc);

        // ---------- column partials over own 32 rows ----------
        if (iter == 0) {   // one true max pass to seed column shifts
            float m0=-1e30f, m1=-1e30f, m2=-1e30f, m3=-1e30f;
#pragma unroll
            for (int r = 0; r < 32; r++) {
                const float ar = S->A2s[r];
                const float* kr = S->K2 + r * RS;
                float2 ka = *(const float2*)(kr + c0);
                float2 kb = *(const float2*)(kr + c2);
                m0 = fmaxf(m0, ka.x + ar);
                m1 = fmaxf(m1, ka.y + ar);
                m2 = fmaxf(m2, kb.x + ar);
                m3 = fmaxf(m3, kb.y + ar);
            }
            S->colShift[c0] = m0; S->colShift[c1] = m1;
            S->colShift[c2] = m2; S->colShift[c3] = m3;
        }
        {
            const float mc0 = S->colShift[c0], mc1 = S->colShift[c1];
            const float mc2 = S->colShift[c2], mc3 = S->colShift[c3];
            float s0 = 0.f, s1 = 0.f, s2 = 0.f, s3 = 0.f;
#pragma unroll
            for (int r = 0; r < 32; r++) {
                const float ar = S->A2s[r];
                const float* kr = S->K2 + r * RS;
                float2 ka = *(const float2*)(kr + c0);
                float2 kb = *(const float2*)(kr + c2);
                s0 += ex2f(ka.x + (ar - mc0));
                s1 += ex2f(ka.y + (ar - mc1));
                s2 += ex2f(kb.x + (ar - mc2));
                s3 += ex2f(kb.y + (ar - mc3));
            }
            *(float4*)(&g_cp[bid * PP + c0]) = make_float4(mc0, s0, mc1, s1);
            *(float4*)(&g_cp[bid * PP + c2]) = make_float4(mc2, s2, mc3, s3);
            // next iteration's column shifts = this CTA's partial LSE
            S->colShift[c0] = mc0 + lg2f(s0);
            S->colShift[c1] = mc1 + lg2f(s1);
            S->colShift[c2] = mc2 + lg2f(s2);
            S->colShift[c3] = mc3 + lg2f(s3);
        }
        gbar(g0 + (++bk), bid);

        // ---------- phase 2: combine own 32 columns (tree) ----------
        {
            const float2* cpb = g_cp + (size_t)(nb * 32) * PP + (sub * 32 + lane);
            float2 p = __ldcg(cpb + warp * PP);
#pragma unroll
            for (int k = 1; k < 4; k++) {
                float2 q = __ldcg(cpb + (warp + 8 * k) * PP);
                float mn = fmaxf(p.x, q.x);
                p.y = p.y * ex2f(p.x - mn) + q.y * ex2f(q.x - mn);
                p.x = mn;
            }
            S->cmb[warp][lane] = p;
        }
        __syncthreads();
        if (warp == 0) {
            float2 p = S->cmb[0][lane];
#pragma unroll
            for (int w = 1; w < 8; w++) {
                float2 q = S->cmb[w][lane];
                float mn = fmaxf(p.x, q.x);
                p.y = p.y * ex2f(p.x - mn) + q.y * ex2f(q.x - mn);
                p.x = mn;
            }
            float B = S->lnu2[sub * 32 + lane] - (p.x + lg2f(p.y));
            __stcg(&g_b2[nb * PP + sub * 32 + lane], B);
        }
        gbar(g0 + (++bk), bid);

        // reload full B vector
        ((float4*)S->bb)[tid] = __ldcg(((const float4*)(g_b2 + nb * PP)) + tid);
        __syncthreads();

        iter++;
        if (iter >= MAXIT) break;
        {
            const float* e = &g_err[(iter - 1) * 4];
            float ev = __ldcg(e + 0) + __ldcg(e + 1) + __ldcg(e + 2) + __ldcg(e + 3);
            if (ev * (EPSV * LN2F * 0.25f) < THRESH) break;
        }
    }

    // ---- final cost: cost_n = -eps*ln2 * sum 2^(K2+A+B) * K2 ----
    {
        const float bc0 = S->bb[c0], bc1 = S->bb[c1];
        const float bc2 = S->bb[c2], bc3 = S->bb[c3];
        float acc = 0.f;
#pragma unroll 8
        for (int r = 0; r < 32; r++) {
            const float ar = S->A2s[r];
            const float* kr = S->K2 + r * RS;
            float2 ka = *(const float2*)(kr + c0);
            float2 kb = *(const float2*)(kr + c2);
            acc = fmaf(ex2f(ka.x + ar + bc0), ka.x, acc);
            acc = fmaf(ex2f(ka.y + ar + bc1), ka.y, acc);
            acc = fmaf(ex2f(kb.x + ar + bc2), kb.x, acc);
            acc = fmaf(ex2f(kb.y + ar + bc3), kb.y, acc);
        }
        S->redd[tid] = (double)acc; __syncthreads();
        for (int s = TPB/2; s > 0; s >>= 1) { if (tid < s) S->redd[tid] += S->redd[tid+s]; __syncthreads(); }
        if (tid == 0) atomicAdd(&g_cost[nb], S->redd[0]);
    }
    gbar(g0 + (++bk), bid);
    if (sub == 0 && tid == 0) {
        double cv = __ldcg(&g_cost[nb]);
        gout[nb] = (float)(-(double)EPSV * (double)LN2F * cv);
    }
}

extern "C" void kernel_launch(void* const* d_in, const int* in_sizes, int n_in,
                              void* d_out, int out_size) {
    const float* x  = (const float*)d_in[0];
    const float* y  = (const float*)d_in[1];
    const float* xw = (const float*)d_in[2];
    const float* yw = (const float*)d_in[3];
    float* out = (float*)d_out;
    size_t smem = sizeof(Smem);
    cudaFuncSetAttribute(sinkhorn_kernel, cudaFuncAttributeMaxDynamicSharedMemorySize, (int)smem);
    sinkhorn_kernel<<<NCTA, TPB, smem>>>(x, y, xw, yw, out);
}